// round 8
// baseline (speedup 1.0000x reference)
#include <cuda_runtime.h>
#include <cstdint>

// ---------------- problem constants ----------------
#define NMAX 100000
#define EMAX 600000
#define FIN  128
#define FHID 128
#define FOUT 64

// ---------------- scratch (static device globals; no allocs) ----------------
__device__ __align__(16) float g_hn[(size_t)NMAX * FHID];   // per-layer GEMM out (pre-agg)
__device__ __align__(16) float g_x2[(size_t)NMAX * FHID];   // layer-2 input
__device__ __align__(16) float g_dinv[NMAX];
__device__ int   g_count[NMAX];
__device__ int   g_start[NMAX];
__device__ int   g_cursor[NMAX];
__device__ int   g_srcsorted[EMAX];
__device__ int   g_total;

// ---------------- degree / CSR build ----------------
__global__ void k_zero(int n) {
    int i = blockIdx.x * blockDim.x + threadIdx.x;
    if (i < n) g_count[i] = 0;
    if (i == 0) g_total = 0;
}

// edge_index is int32, layout [2, E]: src = ei[e], dst = ei[E + e]
// 4 edges per thread for MLP
__global__ void k_hist(const int* __restrict__ ei, int n_edges, int n_nodes) {
    int e = (blockIdx.x * blockDim.x + threadIdx.x) * 4;
    if (e + 4 <= n_edges) {
        int4 d4 = *reinterpret_cast<const int4*>(ei + n_edges + e);
        if ((unsigned)d4.x < (unsigned)n_nodes) atomicAdd(&g_count[d4.x], 1);
        if ((unsigned)d4.y < (unsigned)n_nodes) atomicAdd(&g_count[d4.y], 1);
        if ((unsigned)d4.z < (unsigned)n_nodes) atomicAdd(&g_count[d4.z], 1);
        if ((unsigned)d4.w < (unsigned)n_nodes) atomicAdd(&g_count[d4.w], 1);
    } else {
        for (int i = e; i < n_edges; i++) {
            int d = ei[n_edges + i];
            if ((unsigned)d < (unsigned)n_nodes) atomicAdd(&g_count[d], 1);
        }
    }
}

// ONE-PASS order-free scan: per-block local prefix + atomic base grab.
// Writes start/cursor/dinv.
__global__ void k_scan(int n) {
    __shared__ int s[256];
    __shared__ int base_sh;
    int t = threadIdx.x;
    int blk = blockIdx.x * 1024;
    int vals[4];
    int tsum = 0;
    #pragma unroll
    for (int k = 0; k < 4; k++) {
        int i = blk + t * 4 + k;
        vals[k] = (i < n) ? g_count[i] : 0;
        tsum += vals[k];
    }
    s[t] = tsum;
    __syncthreads();
    for (int off = 1; off < 256; off <<= 1) {
        int x = (t >= off) ? s[t - off] : 0;
        __syncthreads();
        s[t] += x;
        __syncthreads();
    }
    if (t == 255) base_sh = atomicAdd(&g_total, s[255]);
    __syncthreads();
    int texcl = s[t] - tsum + base_sh;
    int run = 0;
    #pragma unroll
    for (int k = 0; k < 4; k++) {
        int i = blk + t * 4 + k;
        if (i < n) {
            int o = texcl + run;
            g_start[i]  = o;
            g_cursor[i] = o;
            g_dinv[i]   = rsqrtf((float)(vals[k] + 1));   // +1 self loop
        }
        run += vals[k];
    }
}

// 4 edges per thread
__global__ void k_fill(const int* __restrict__ ei, int n_edges, int n_nodes) {
    int e = (blockIdx.x * blockDim.x + threadIdx.x) * 4;
    if (e + 4 <= n_edges) {
        int4 s4 = *reinterpret_cast<const int4*>(ei + e);
        int4 d4 = *reinterpret_cast<const int4*>(ei + n_edges + e);
        if ((unsigned)d4.x < (unsigned)n_nodes && (unsigned)s4.x < (unsigned)n_nodes)
            g_srcsorted[atomicAdd(&g_cursor[d4.x], 1)] = s4.x;
        if ((unsigned)d4.y < (unsigned)n_nodes && (unsigned)s4.y < (unsigned)n_nodes)
            g_srcsorted[atomicAdd(&g_cursor[d4.y], 1)] = s4.y;
        if ((unsigned)d4.z < (unsigned)n_nodes && (unsigned)s4.z < (unsigned)n_nodes)
            g_srcsorted[atomicAdd(&g_cursor[d4.z], 1)] = s4.z;
        if ((unsigned)d4.w < (unsigned)n_nodes && (unsigned)s4.w < (unsigned)n_nodes)
            g_srcsorted[atomicAdd(&g_cursor[d4.w], 1)] = s4.w;
    } else {
        for (int i = e; i < n_edges; i++) {
            int srcv = ei[i], d = ei[n_edges + i];
            if ((unsigned)d < (unsigned)n_nodes && (unsigned)srcv < (unsigned)n_nodes)
                g_srcsorted[atomicAdd(&g_cursor[d], 1)] = srcv;
        }
    }
}

// ---------------- TF32 helpers ----------------
__device__ __forceinline__ float to_tf32(float x) {
    uint32_t u;
    asm("cvt.rna.tf32.f32 %0, %1;" : "=r"(u) : "f"(x));
    return __uint_as_float(u);
}

__device__ __forceinline__ void mma_tf32(float c[4], const float a[4], float b0, float b1) {
    uint32_t const* A = reinterpret_cast<uint32_t const*>(a);
    uint32_t B0 = __float_as_uint(b0), B1 = __float_as_uint(b1);
    asm volatile(
        "mma.sync.aligned.m16n8k8.row.col.f32.tf32.tf32.f32 "
        "{%0,%1,%2,%3}, {%4,%5,%6,%7}, {%8,%9}, {%0,%1,%2,%3};"
        : "+f"(c[0]), "+f"(c[1]), "+f"(c[2]), "+f"(c[3])
        : "r"(A[0]), "r"(A[1]), "r"(A[2]), "r"(A[3]), "r"(B0), "r"(B1));
}

// ---------------- TF32 tensor-core GEMM ----------------
// g_hn[m,n] = scale * sum_k A[m,k]*B[k,n]
// DINV=1: multiply rows by g_dinv[m] in epilogue (layer 2). DINV=0: no scaling (layer 1,
// so the GEMM has no dependency on the CSR/degree chain and can run concurrently).
template <int BN, int SRC, int DINV>
__global__ void __launch_bounds__(256)
k_mma(const float* __restrict__ Aext, const float* __restrict__ Bg,
      int M, int K) {
    const float* __restrict__ A = (SRC == 0) ? Aext : g_x2;
    const int KC = 32;
    const int APITCH = KC + 4;        // 36
    const int BPITCH = BN + 8;
    __shared__ float As[128 * APITCH];
    __shared__ float Bs[KC * BPITCH];

    int tid  = threadIdx.x;
    int warp = tid >> 5, lane = tid & 31;
    int wm = warp & 3, wn = warp >> 2;
    const int WNT = BN / 2;
    const int NF  = WNT / 8;
    int g  = lane >> 2, tg = lane & 3;
    int row0 = blockIdx.x * 128;

    float acc[2][NF][4];
    #pragma unroll
    for (int i = 0; i < 2; i++)
        #pragma unroll
        for (int j = 0; j < NF; j++)
            #pragma unroll
            for (int q = 0; q < 4; q++) acc[i][j][q] = 0.0f;

    for (int k0 = 0; k0 < K; k0 += KC) {
        {   // stage A [128 x 32]
            int r = tid >> 3, c = (tid & 7) * 4;
            #pragma unroll
            for (int i = 0; i < 4; i++) {
                int rr = r + i * 32;
                float4 v = make_float4(0.f, 0.f, 0.f, 0.f);
                if (row0 + rr < M)
                    v = *reinterpret_cast<const float4*>(A + (size_t)(row0 + rr) * K + k0 + c);
                v.x = to_tf32(v.x); v.y = to_tf32(v.y);
                v.z = to_tf32(v.z); v.w = to_tf32(v.w);
                *reinterpret_cast<float4*>(&As[rr * APITCH + c]) = v;
            }
        }
        {   // stage B [32 x BN]
            const int TPR = BN / 4;
            int kr = tid / TPR, bc = (tid % TPR) * 4;
            const int KSTEP = 256 / TPR;
            #pragma unroll
            for (int i = 0; i < KC / KSTEP; i++) {
                int kk = kr + i * KSTEP;
                float4 v = *reinterpret_cast<const float4*>(Bg + (size_t)(k0 + kk) * BN + bc);
                v.x = to_tf32(v.x); v.y = to_tf32(v.y);
                v.z = to_tf32(v.z); v.w = to_tf32(v.w);
                *reinterpret_cast<float4*>(&Bs[kk * BPITCH + bc]) = v;
            }
        }
        __syncthreads();

        #pragma unroll
        for (int ks = 0; ks < KC; ks += 8) {
            float a[2][4];
            #pragma unroll
            for (int mf = 0; mf < 2; mf++) {
                int ar = wm * 32 + mf * 16;
                a[mf][0] = As[(ar + g)     * APITCH + ks + tg];
                a[mf][1] = As[(ar + g + 8) * APITCH + ks + tg];
                a[mf][2] = As[(ar + g)     * APITCH + ks + tg + 4];
                a[mf][3] = As[(ar + g + 8) * APITCH + ks + tg + 4];
            }
            #pragma unroll
            for (int nf = 0; nf < NF; nf++) {
                int bn0 = wn * WNT + nf * 8;
                float b0 = Bs[(ks + tg)     * BPITCH + bn0 + g];
                float b1 = Bs[(ks + tg + 4) * BPITCH + bn0 + g];
                #pragma unroll
                for (int mf = 0; mf < 2; mf++)
                    mma_tf32(acc[mf][nf], a[mf], b0, b1);
            }
        }
        __syncthreads();
    }

    #pragma unroll
    for (int mf = 0; mf < 2; mf++) {
        int r0 = row0 + wm * 32 + mf * 16 + g;
        int r1 = r0 + 8;
        float d0 = 1.f, d1 = 1.f;
        if (DINV) {
            d0 = (r0 < M) ? g_dinv[r0] : 0.f;
            d1 = (r1 < M) ? g_dinv[r1] : 0.f;
        }
        #pragma unroll
        for (int nf = 0; nf < NF; nf++) {
            int cc = wn * WNT + nf * 8 + tg * 2;
            if (r0 < M) {
                g_hn[(size_t)r0 * BN + cc]     = acc[mf][nf][0] * d0;
                g_hn[(size_t)r0 * BN + cc + 1] = acc[mf][nf][1] * d0;
            }
            if (r1 < M) {
                g_hn[(size_t)r1 * BN + cc]     = acc[mf][nf][2] * d1;
                g_hn[(size_t)r1 * BN + cc + 1] = acc[mf][nf][3] * d1;
            }
        }
    }
}

// ---------------- layer-1 aggregation (hn is UNSCALED X@W1) ----------------
// x2[d] = relu( dinv[d]*( hn[d]*dinv[d] + sum_s hn[s]*dinv[s] ) + b1 )
__global__ void k_agg128(const float* __restrict__ bias, int n_nodes) {
    int warp = (blockIdx.x * blockDim.x + threadIdx.x) >> 5;
    int lane = threadIdx.x & 31;
    if (warp >= n_nodes) return;
    int d = warp;
    const float* hn = g_hn;
    float dv = g_dinv[d];
    float4 h = *reinterpret_cast<const float4*>(hn + (size_t)d * 128 + lane * 4);
    float4 acc, acc2 = make_float4(0.f, 0.f, 0.f, 0.f);
    acc.x = h.x * dv; acc.y = h.y * dv; acc.z = h.z * dv; acc.w = h.w * dv;
    int e = g_start[d], e1 = e + g_count[d];
    for (; e + 4 <= e1; e += 4) {
        int s0 = g_srcsorted[e],     s1 = g_srcsorted[e + 1];
        int s2 = g_srcsorted[e + 2], s3 = g_srcsorted[e + 3];
        float w0 = g_dinv[s0], w1 = g_dinv[s1], w2 = g_dinv[s2], w3 = g_dinv[s3];
        float4 v0 = *reinterpret_cast<const float4*>(hn + (size_t)s0 * 128 + lane * 4);
        float4 v1 = *reinterpret_cast<const float4*>(hn + (size_t)s1 * 128 + lane * 4);
        float4 v2 = *reinterpret_cast<const float4*>(hn + (size_t)s2 * 128 + lane * 4);
        float4 v3 = *reinterpret_cast<const float4*>(hn + (size_t)s3 * 128 + lane * 4);
        acc.x  = fmaf(v0.x, w0, acc.x);  acc.y  = fmaf(v0.y, w0, acc.y);
        acc.z  = fmaf(v0.z, w0, acc.z);  acc.w  = fmaf(v0.w, w0, acc.w);
        acc2.x = fmaf(v1.x, w1, acc2.x); acc2.y = fmaf(v1.y, w1, acc2.y);
        acc2.z = fmaf(v1.z, w1, acc2.z); acc2.w = fmaf(v1.w, w1, acc2.w);
        acc.x  = fmaf(v2.x, w2, acc.x);  acc.y  = fmaf(v2.y, w2, acc.y);
        acc.z  = fmaf(v2.z, w2, acc.z);  acc.w  = fmaf(v2.w, w2, acc.w);
        acc2.x = fmaf(v3.x, w3, acc2.x); acc2.y = fmaf(v3.y, w3, acc2.y);
        acc2.z = fmaf(v3.z, w3, acc2.z); acc2.w = fmaf(v3.w, w3, acc2.w);
    }
    for (; e < e1; e++) {
        int s = g_srcsorted[e];
        float w = g_dinv[s];
        float4 v = *reinterpret_cast<const float4*>(hn + (size_t)s * 128 + lane * 4);
        acc.x = fmaf(v.x, w, acc.x); acc.y = fmaf(v.y, w, acc.y);
        acc.z = fmaf(v.z, w, acc.z); acc.w = fmaf(v.w, w, acc.w);
    }
    acc.x += acc2.x; acc.y += acc2.y; acc.z += acc2.z; acc.w += acc2.w;
    float4 bv = *reinterpret_cast<const float4*>(bias + lane * 4);
    float4 o;
    o.x = fmaxf(fmaf(acc.x, dv, bv.x), 0.f);
    o.y = fmaxf(fmaf(acc.y, dv, bv.y), 0.f);
    o.z = fmaxf(fmaf(acc.z, dv, bv.z), 0.f);
    o.w = fmaxf(fmaf(acc.w, dv, bv.w), 0.f);
    *reinterpret_cast<float4*>(g_x2 + (size_t)d * 128 + lane * 4) = o;
}

// layer 2: hn2 = dinv*(x2@W2) already scaled; out = dinv[d]*(hn2[d] + sum hn2[s]) + b2
__global__ void k_agg64(const float* __restrict__ bias,
                        float* __restrict__ out, int n_nodes) {
    int warp = (blockIdx.x * blockDim.x + threadIdx.x) >> 5;
    int lane = threadIdx.x & 31;
    if (warp >= n_nodes) return;
    int d = warp;
    const float* hn = g_hn;
    float2 acc = *reinterpret_cast<const float2*>(hn + (size_t)d * 64 + lane * 2);
    float2 acc2 = make_float2(0.f, 0.f);
    int e = g_start[d], e1 = e + g_count[d];
    for (; e + 4 <= e1; e += 4) {
        int s0 = g_srcsorted[e],     s1 = g_srcsorted[e + 1];
        int s2 = g_srcsorted[e + 2], s3 = g_srcsorted[e + 3];
        float2 v0 = *reinterpret_cast<const float2*>(hn + (size_t)s0 * 64 + lane * 2);
        float2 v1 = *reinterpret_cast<const float2*>(hn + (size_t)s1 * 64 + lane * 2);
        float2 v2 = *reinterpret_cast<const float2*>(hn + (size_t)s2 * 64 + lane * 2);
        float2 v3 = *reinterpret_cast<const float2*>(hn + (size_t)s3 * 64 + lane * 2);
        acc.x += v0.x; acc.y += v0.y;
        acc2.x += v1.x; acc2.y += v1.y;
        acc.x += v2.x; acc.y += v2.y;
        acc2.x += v3.x; acc2.y += v3.y;
    }
    for (; e < e1; e++) {
        int s = g_srcsorted[e];
        float2 v = *reinterpret_cast<const float2*>(hn + (size_t)s * 64 + lane * 2);
        acc.x += v.x; acc.y += v.y;
    }
    acc.x += acc2.x; acc.y += acc2.y;
    float dv = g_dinv[d];
    float2 bv = *reinterpret_cast<const float2*>(bias + lane * 2);
    float2 o;
    o.x = fmaf(acc.x, dv, bv.x);
    o.y = fmaf(acc.y, dv, bv.y);
    *reinterpret_cast<float2*>(out + (size_t)d * 64 + lane * 2) = o;
}

// ---------------- launch ----------------
extern "C" void kernel_launch(void* const* d_in, const int* in_sizes, int n_in,
                              void* d_out, int out_size) {
    const float* x  = (const float*)d_in[0];
    const int*   ei = (const int*)d_in[1];     // int32 [2, E]
    const float* W1 = (const float*)d_in[2];
    const float* b1 = (const float*)d_in[3];
    const float* W2 = (const float*)d_in[4];
    const float* b2 = (const float*)d_in[5];
    float* out = (float*)d_out;

    int n_nodes = in_sizes[0] / FIN;       // 100000
    int n_edges = in_sizes[1] / 2;         // 600000

    int nb_nodes  = (n_nodes + 255) / 256;
    int nb_edges4 = ((n_edges + 3) / 4 + 255) / 256;
    int nb_scan   = (n_nodes + 1023) / 1024;
    int nb_gemm   = (n_nodes + 127) / 128;
    int nb_agg    = (n_nodes * 32 + 255) / 256;

    // one-time stream/event creation (first call is the uncaptured correctness run)
    static cudaStream_t s2 = nullptr;
    static cudaEvent_t evFork = nullptr, evJoin = nullptr;
    if (!s2) {
        cudaStreamCreateWithFlags(&s2, cudaStreamNonBlocking);
        cudaEventCreateWithFlags(&evFork, cudaEventDisableTiming);
        cudaEventCreateWithFlags(&evJoin, cudaEventDisableTiming);
    }

    // ---- fork: CSR chain on s2, GEMM1 (CSR-independent) on main stream ----
    cudaEventRecord(evFork, 0);
    cudaStreamWaitEvent(s2, evFork, 0);

    k_zero<<<nb_nodes, 256, 0, s2>>>(n_nodes);
    k_hist<<<nb_edges4, 256, 0, s2>>>(ei, n_edges, n_nodes);
    k_scan<<<nb_scan, 256, 0, s2>>>(n_nodes);
    k_fill<<<nb_edges4, 256, 0, s2>>>(ei, n_edges, n_nodes);
    cudaEventRecord(evJoin, s2);

    k_mma<FHID, 0, 0><<<nb_gemm, 256>>>(x, W1, n_nodes, FIN);   // hn = X@W1 (no dinv)

    cudaStreamWaitEvent(0, evJoin, 0);   // join: CSR + degrees ready

    // ---- layer 1 aggregation (applies dinv on both sides) ----
    k_agg128<<<nb_agg, 256>>>(b1, n_nodes);

    // ---- layer 2: hn = dinv*(x2@W2) ; out = dinv*agg + b2 ----
    k_mma<FOUT, 1, 1><<<nb_gemm, 256>>>(nullptr, W2, n_nodes, FHID);
    k_agg64<<<nb_agg, 256>>>(b2, out, n_nodes);
}

// round 9
// speedup vs baseline: 1.0590x; 1.0590x over previous
#include <cuda_runtime.h>
#include <cstdint>

// ---------------- problem constants ----------------
#define NMAX 100000
#define EMAX 600000
#define FIN  128
#define FHID 128
#define FOUT 64

// ---------------- scratch (static device globals; zero-initialized at load) ----------------
__device__ __align__(16) float g_hn[(size_t)NMAX * FHID];   // per-layer GEMM out (pre-agg)
__device__ __align__(16) float g_x2[(size_t)NMAX * FHID];   // layer-2 input
__device__ __align__(16) float g_dinv[NMAX];
__device__ int   g_count[NMAX];     // zeroed by k_scan after reading (self-cleaning)
__device__ int   g_start[NMAX];
__device__ int   g_end[NMAX];
__device__ int   g_cursor[NMAX];
__device__ int   g_srcsorted[EMAX];
__device__ int   g_total;           // zeroed by k_fill after scan consumed it

// ---------------- degree / CSR build ----------------
// edge_index is int32, layout [2, E]: src = ei[e], dst = ei[E + e]
__global__ void k_hist(const int* __restrict__ ei, int n_edges, int n_nodes) {
    int e = blockIdx.x * blockDim.x + threadIdx.x;
    if (e < n_edges) {
        int d = ei[n_edges + e];
        if ((unsigned)d < (unsigned)n_nodes) atomicAdd(&g_count[d], 1);
    }
}

// ONE-PASS order-free scan: per-block local prefix + atomic base grab.
// Consumes g_count (re-zeros it for the next replay), writes start/end/cursor/dinv.
__global__ void k_scan(int n) {
    __shared__ int s[256];
    __shared__ int base_sh;
    int t = threadIdx.x;
    int blk = blockIdx.x * 1024;
    int vals[4];
    int tsum = 0;
    #pragma unroll
    for (int k = 0; k < 4; k++) {
        int i = blk + t * 4 + k;
        vals[k] = (i < n) ? g_count[i] : 0;
        tsum += vals[k];
    }
    s[t] = tsum;
    __syncthreads();
    for (int off = 1; off < 256; off <<= 1) {
        int x = (t >= off) ? s[t - off] : 0;
        __syncthreads();
        s[t] += x;
        __syncthreads();
    }
    if (t == 255) base_sh = atomicAdd(&g_total, s[255]);
    __syncthreads();
    int texcl = s[t] - tsum + base_sh;
    int run = 0;
    #pragma unroll
    for (int k = 0; k < 4; k++) {
        int i = blk + t * 4 + k;
        if (i < n) {
            int o = texcl + run;
            g_start[i]  = o;
            g_end[i]    = o + vals[k];
            g_cursor[i] = o;
            g_dinv[i]   = rsqrtf((float)(vals[k] + 1));   // +1 self loop
            g_count[i]  = 0;                              // self-clean for next replay
        }
        run += vals[k];
    }
}

__global__ void k_fill(const int* __restrict__ ei, int n_edges, int n_nodes) {
    int e = blockIdx.x * blockDim.x + threadIdx.x;
    if (e == 0) g_total = 0;        // self-clean (scan already consumed it)
    if (e < n_edges) {
        int srcv = ei[e];
        int d    = ei[n_edges + e];
        if ((unsigned)d < (unsigned)n_nodes && (unsigned)srcv < (unsigned)n_nodes) {
            int p = atomicAdd(&g_cursor[d], 1);
            g_srcsorted[p] = srcv;
        }
    }
}

// ---------------- TF32 helpers ----------------
__device__ __forceinline__ float to_tf32(float x) {
    uint32_t u;
    asm("cvt.rna.tf32.f32 %0, %1;" : "=r"(u) : "f"(x));
    return __uint_as_float(u);
}

__device__ __forceinline__ void mma_tf32(float c[4], const float a[4], float b0, float b1) {
    uint32_t const* A = reinterpret_cast<uint32_t const*>(a);
    uint32_t B0 = __float_as_uint(b0), B1 = __float_as_uint(b1);
    asm volatile(
        "mma.sync.aligned.m16n8k8.row.col.f32.tf32.tf32.f32 "
        "{%0,%1,%2,%3}, {%4,%5,%6,%7}, {%8,%9}, {%0,%1,%2,%3};"
        : "+f"(c[0]), "+f"(c[1]), "+f"(c[2]), "+f"(c[3])
        : "r"(A[0]), "r"(A[1]), "r"(A[2]), "r"(A[3]), "r"(B0), "r"(B1));
}

// ---------------- TF32 tensor-core GEMM with fused dinv epilogue ----------------
// g_hn[m,n] = g_dinv[m] * sum_k A[m,k]*B[k,n]
// A = external pointer (SRC=0) or g_x2 (SRC=1). BN = N (128 or 64), K multiple of 32.
template <int BN, int SRC>
__global__ void __launch_bounds__(256)
k_mma_dinv(const float* __restrict__ Aext, const float* __restrict__ Bg,
           int M, int K) {
    const float* __restrict__ A = (SRC == 0) ? Aext : g_x2;
    const int KC = 32;
    const int APITCH = KC + 4;        // 36
    const int BPITCH = BN + 8;
    __shared__ float As[128 * APITCH];
    __shared__ float Bs[KC * BPITCH];

    int tid  = threadIdx.x;
    int warp = tid >> 5, lane = tid & 31;
    int wm = warp & 3, wn = warp >> 2;
    const int WNT = BN / 2;
    const int NF  = WNT / 8;
    int g  = lane >> 2, tg = lane & 3;
    int row0 = blockIdx.x * 128;

    float acc[2][NF][4];
    #pragma unroll
    for (int i = 0; i < 2; i++)
        #pragma unroll
        for (int j = 0; j < NF; j++)
            #pragma unroll
            for (int q = 0; q < 4; q++) acc[i][j][q] = 0.0f;

    for (int k0 = 0; k0 < K; k0 += KC) {
        {   // stage A [128 x 32]
            int r = tid >> 3, c = (tid & 7) * 4;
            #pragma unroll
            for (int i = 0; i < 4; i++) {
                int rr = r + i * 32;
                float4 v = make_float4(0.f, 0.f, 0.f, 0.f);
                if (row0 + rr < M)
                    v = *reinterpret_cast<const float4*>(A + (size_t)(row0 + rr) * K + k0 + c);
                v.x = to_tf32(v.x); v.y = to_tf32(v.y);
                v.z = to_tf32(v.z); v.w = to_tf32(v.w);
                *reinterpret_cast<float4*>(&As[rr * APITCH + c]) = v;
            }
        }
        {   // stage B [32 x BN]
            const int TPR = BN / 4;
            int kr = tid / TPR, bc = (tid % TPR) * 4;
            const int KSTEP = 256 / TPR;
            #pragma unroll
            for (int i = 0; i < KC / KSTEP; i++) {
                int kk = kr + i * KSTEP;
                float4 v = *reinterpret_cast<const float4*>(Bg + (size_t)(k0 + kk) * BN + bc);
                v.x = to_tf32(v.x); v.y = to_tf32(v.y);
                v.z = to_tf32(v.z); v.w = to_tf32(v.w);
                *reinterpret_cast<float4*>(&Bs[kk * BPITCH + bc]) = v;
            }
        }
        __syncthreads();

        #pragma unroll
        for (int ks = 0; ks < KC; ks += 8) {
            float a[2][4];
            #pragma unroll
            for (int mf = 0; mf < 2; mf++) {
                int ar = wm * 32 + mf * 16;
                a[mf][0] = As[(ar + g)     * APITCH + ks + tg];
                a[mf][1] = As[(ar + g + 8) * APITCH + ks + tg];
                a[mf][2] = As[(ar + g)     * APITCH + ks + tg + 4];
                a[mf][3] = As[(ar + g + 8) * APITCH + ks + tg + 4];
            }
            #pragma unroll
            for (int nf = 0; nf < NF; nf++) {
                int bn0 = wn * WNT + nf * 8;
                float b0 = Bs[(ks + tg)     * BPITCH + bn0 + g];
                float b1 = Bs[(ks + tg + 4) * BPITCH + bn0 + g];
                #pragma unroll
                for (int mf = 0; mf < 2; mf++)
                    mma_tf32(acc[mf][nf], a[mf], b0, b1);
            }
        }
        __syncthreads();
    }

    #pragma unroll
    for (int mf = 0; mf < 2; mf++) {
        int r0 = row0 + wm * 32 + mf * 16 + g;
        int r1 = r0 + 8;
        float d0 = (r0 < M) ? g_dinv[r0] : 0.f;
        float d1 = (r1 < M) ? g_dinv[r1] : 0.f;
        #pragma unroll
        for (int nf = 0; nf < NF; nf++) {
            int cc = wn * WNT + nf * 8 + tg * 2;
            if (r0 < M) {
                g_hn[(size_t)r0 * BN + cc]     = acc[mf][nf][0] * d0;
                g_hn[(size_t)r0 * BN + cc + 1] = acc[mf][nf][1] * d0;
            }
            if (r1 < M) {
                g_hn[(size_t)r1 * BN + cc]     = acc[mf][nf][2] * d1;
                g_hn[(size_t)r1 * BN + cc + 1] = acc[mf][nf][3] * d1;
            }
        }
    }
}

// ---------------- aggregation: one warp per node, MLP-4 gathers ----------------
// x2[d] = relu( dinv[d]*(hn[d] + sum_{s in N(d)} hn[s]) + b1 )   (F=128, hn pre-scaled)
__global__ void k_agg128(const float* __restrict__ bias, int n_nodes) {
    int warp = (blockIdx.x * blockDim.x + threadIdx.x) >> 5;
    int lane = threadIdx.x & 31;
    if (warp >= n_nodes) return;
    int d = warp;
    const float* hn = g_hn;
    float4 acc = *reinterpret_cast<const float4*>(hn + (size_t)d * 128 + lane * 4);
    float4 acc2 = make_float4(0.f, 0.f, 0.f, 0.f);
    int e = g_start[d], e1 = g_end[d];
    for (; e + 4 <= e1; e += 4) {
        int s0 = g_srcsorted[e],     s1 = g_srcsorted[e + 1];
        int s2 = g_srcsorted[e + 2], s3 = g_srcsorted[e + 3];
        float4 v0 = *reinterpret_cast<const float4*>(hn + (size_t)s0 * 128 + lane * 4);
        float4 v1 = *reinterpret_cast<const float4*>(hn + (size_t)s1 * 128 + lane * 4);
        float4 v2 = *reinterpret_cast<const float4*>(hn + (size_t)s2 * 128 + lane * 4);
        float4 v3 = *reinterpret_cast<const float4*>(hn + (size_t)s3 * 128 + lane * 4);
        acc.x += v0.x; acc.y += v0.y; acc.z += v0.z; acc.w += v0.w;
        acc2.x += v1.x; acc2.y += v1.y; acc2.z += v1.z; acc2.w += v1.w;
        acc.x += v2.x; acc.y += v2.y; acc.z += v2.z; acc.w += v2.w;
        acc2.x += v3.x; acc2.y += v3.y; acc2.z += v3.z; acc2.w += v3.w;
    }
    for (; e < e1; e++) {
        int s = g_srcsorted[e];
        float4 v = *reinterpret_cast<const float4*>(hn + (size_t)s * 128 + lane * 4);
        acc.x += v.x; acc.y += v.y; acc.z += v.z; acc.w += v.w;
    }
    acc.x += acc2.x; acc.y += acc2.y; acc.z += acc2.z; acc.w += acc2.w;
    float dv = g_dinv[d];
    float4 bv = *reinterpret_cast<const float4*>(bias + lane * 4);
    float4 o;
    o.x = fmaxf(fmaf(acc.x, dv, bv.x), 0.f);
    o.y = fmaxf(fmaf(acc.y, dv, bv.y), 0.f);
    o.z = fmaxf(fmaf(acc.z, dv, bv.z), 0.f);
    o.w = fmaxf(fmaf(acc.w, dv, bv.w), 0.f);
    *reinterpret_cast<float4*>(g_x2 + (size_t)d * 128 + lane * 4) = o;
}

// out[d] = dinv[d]*(hn[d] + sum hn[s]) + b2   (F=64, no relu, hn pre-scaled)
__global__ void k_agg64(const float* __restrict__ bias,
                        float* __restrict__ out, int n_nodes) {
    int warp = (blockIdx.x * blockDim.x + threadIdx.x) >> 5;
    int lane = threadIdx.x & 31;
    if (warp >= n_nodes) return;
    int d = warp;
    const float* hn = g_hn;
    float2 acc = *reinterpret_cast<const float2*>(hn + (size_t)d * 64 + lane * 2);
    float2 acc2 = make_float2(0.f, 0.f);
    int e = g_start[d], e1 = g_end[d];
    for (; e + 4 <= e1; e += 4) {
        int s0 = g_srcsorted[e],     s1 = g_srcsorted[e + 1];
        int s2 = g_srcsorted[e + 2], s3 = g_srcsorted[e + 3];
        float2 v0 = *reinterpret_cast<const float2*>(hn + (size_t)s0 * 64 + lane * 2);
        float2 v1 = *reinterpret_cast<const float2*>(hn + (size_t)s1 * 64 + lane * 2);
        float2 v2 = *reinterpret_cast<const float2*>(hn + (size_t)s2 * 64 + lane * 2);
        float2 v3 = *reinterpret_cast<const float2*>(hn + (size_t)s3 * 64 + lane * 2);
        acc.x += v0.x; acc.y += v0.y;
        acc2.x += v1.x; acc2.y += v1.y;
        acc.x += v2.x; acc.y += v2.y;
        acc2.x += v3.x; acc2.y += v3.y;
    }
    for (; e < e1; e++) {
        int s = g_srcsorted[e];
        float2 v = *reinterpret_cast<const float2*>(hn + (size_t)s * 64 + lane * 2);
        acc.x += v.x; acc.y += v.y;
    }
    acc.x += acc2.x; acc.y += acc2.y;
    float dv = g_dinv[d];
    float2 bv = *reinterpret_cast<const float2*>(bias + lane * 2);
    float2 o;
    o.x = fmaf(acc.x, dv, bv.x);
    o.y = fmaf(acc.y, dv, bv.y);
    *reinterpret_cast<float2*>(out + (size_t)d * 64 + lane * 2) = o;
}

// ---------------- launch ----------------
extern "C" void kernel_launch(void* const* d_in, const int* in_sizes, int n_in,
                              void* d_out, int out_size) {
    const float* x  = (const float*)d_in[0];
    const int*   ei = (const int*)d_in[1];     // int32 [2, E]
    const float* W1 = (const float*)d_in[2];
    const float* b1 = (const float*)d_in[3];
    const float* W2 = (const float*)d_in[4];
    const float* b2 = (const float*)d_in[5];
    float* out = (float*)d_out;

    int n_nodes = in_sizes[0] / FIN;       // 100000
    int n_edges = in_sizes[1] / 2;         // 600000

    int nb_edges = (n_edges + 255) / 256;
    int nb_scan  = (n_nodes + 1023) / 1024;
    int nb_gemm  = (n_nodes + 127) / 128;
    int nb_agg   = (n_nodes * 32 + 255) / 256;

    // one-time stream/event creation (first call is the uncaptured correctness run)
    static cudaStream_t s2 = nullptr;
    static cudaEvent_t evFork = nullptr, evJoin = nullptr;
    if (!s2) {
        cudaStreamCreateWithFlags(&s2, cudaStreamNonBlocking);
        cudaEventCreateWithFlags(&evFork, cudaEventDisableTiming);
        cudaEventCreateWithFlags(&evJoin, cudaEventDisableTiming);
    }

    // ---- CSR: hist -> scan (main stream; GEMM1 needs dinv from scan) ----
    k_hist<<<nb_edges, 256>>>(ei, n_edges, n_nodes);
    k_scan<<<nb_scan, 256>>>(n_nodes);

    // ---- narrow fork: fill (s2) overlaps GEMM1 (main) ----
    cudaEventRecord(evFork, 0);
    cudaStreamWaitEvent(s2, evFork, 0);
    k_fill<<<nb_edges, 256, 0, s2>>>(ei, n_edges, n_nodes);
    cudaEventRecord(evJoin, s2);

    k_mma_dinv<FHID, 0><<<nb_gemm, 256>>>(x, W1, n_nodes, FIN);   // hn = dinv*(X@W1)

    cudaStreamWaitEvent(0, evJoin, 0);   // join: adjacency ready

    // ---- layer 1 aggregation ----
    k_agg128<<<nb_agg, 256>>>(b1, n_nodes);

    // ---- layer 2 ----
    k_mma_dinv<FOUT, 1><<<nb_gemm, 256>>>(nullptr, W2, n_nodes, FHID);
    k_agg64<<<nb_agg, 256>>>(b2, out, n_nodes);
}

// round 10
// speedup vs baseline: 1.1743x; 1.1090x over previous
#include <cuda_runtime.h>
#include <cstdint>

// ---------------- problem constants ----------------
#define NMAX 100000
#define EMAX 600000
#define FIN  128
#define FHID 128
#define FOUT 64

// ---------------- scratch (static device globals; zero-initialized at load) ----------------
__device__ __align__(16) float g_hn[(size_t)NMAX * FHID];   // per-layer GEMM out (pre-agg)
__device__ __align__(16) float g_x2[(size_t)NMAX * FHID];   // layer-2 input
__device__ __align__(16) float g_dinv[NMAX];
__device__ int   g_count[NMAX];     // zeroed by k_scan after reading (self-cleaning)
__device__ int   g_start[NMAX];
__device__ int   g_end[NMAX];
__device__ int   g_cursor[NMAX];
__device__ int   g_srcsorted[EMAX];
__device__ int   g_total;           // zeroed by k_fill after scan consumed it

// ---------------- degree / CSR build ----------------
// edge_index is int32, layout [2, E]: src = ei[e], dst = ei[E + e]
__global__ void k_hist(const int* __restrict__ ei, int n_edges, int n_nodes) {
    int e = blockIdx.x * blockDim.x + threadIdx.x;
    if (e < n_edges) {
        int d = ei[n_edges + e];
        if ((unsigned)d < (unsigned)n_nodes) atomicAdd(&g_count[d], 1);
    }
}

// ONE-PASS order-free scan: per-block local prefix + atomic base grab.
// Consumes g_count (re-zeros it for the next replay), writes start/end/cursor/dinv.
__global__ void k_scan(int n) {
    __shared__ int s[256];
    __shared__ int base_sh;
    int t = threadIdx.x;
    int blk = blockIdx.x * 1024;
    int vals[4];
    int tsum = 0;
    #pragma unroll
    for (int k = 0; k < 4; k++) {
        int i = blk + t * 4 + k;
        vals[k] = (i < n) ? g_count[i] : 0;
        tsum += vals[k];
    }
    s[t] = tsum;
    __syncthreads();
    for (int off = 1; off < 256; off <<= 1) {
        int x = (t >= off) ? s[t - off] : 0;
        __syncthreads();
        s[t] += x;
        __syncthreads();
    }
    if (t == 255) base_sh = atomicAdd(&g_total, s[255]);
    __syncthreads();
    int texcl = s[t] - tsum + base_sh;
    int run = 0;
    #pragma unroll
    for (int k = 0; k < 4; k++) {
        int i = blk + t * 4 + k;
        if (i < n) {
            int o = texcl + run;
            g_start[i]  = o;
            g_end[i]    = o + vals[k];
            g_cursor[i] = o;
            g_dinv[i]   = rsqrtf((float)(vals[k] + 1));   // +1 self loop
            g_count[i]  = 0;                              // self-clean for next replay
        }
        run += vals[k];
    }
}

__global__ void k_fill(const int* __restrict__ ei, int n_edges, int n_nodes) {
    int e = blockIdx.x * blockDim.x + threadIdx.x;
    if (e == 0) g_total = 0;        // self-clean (scan already consumed it)
    if (e < n_edges) {
        int srcv = ei[e];
        int d    = ei[n_edges + e];
        if ((unsigned)d < (unsigned)n_nodes && (unsigned)srcv < (unsigned)n_nodes) {
            int p = atomicAdd(&g_cursor[d], 1);
            g_srcsorted[p] = srcv;
        }
    }
}

// ---------------- TF32 helpers ----------------
__device__ __forceinline__ float to_tf32(float x) {
    uint32_t u;
    asm("cvt.rna.tf32.f32 %0, %1;" : "=r"(u) : "f"(x));
    return __uint_as_float(u);
}

__device__ __forceinline__ float4 cvt4(float4 v) {
    v.x = to_tf32(v.x); v.y = to_tf32(v.y);
    v.z = to_tf32(v.z); v.w = to_tf32(v.w);
    return v;
}

__device__ __forceinline__ void mma_tf32(float c[4], const float a[4], float b0, float b1) {
    uint32_t const* A = reinterpret_cast<uint32_t const*>(a);
    uint32_t B0 = __float_as_uint(b0), B1 = __float_as_uint(b1);
    asm volatile(
        "mma.sync.aligned.m16n8k8.row.col.f32.tf32.tf32.f32 "
        "{%0,%1,%2,%3}, {%4,%5,%6,%7}, {%8,%9}, {%0,%1,%2,%3};"
        : "+f"(c[0]), "+f"(c[1]), "+f"(c[2]), "+f"(c[3])
        : "r"(A[0]), "r"(A[1]), "r"(A[2]), "r"(A[3]), "r"(B0), "r"(B1));
}

// ---------------- double-buffered TF32 GEMM with fused dinv epilogue ----------------
// g_hn[m,n] = g_dinv[m] * sum_k A[m,k]*B[k,n]
// Software pipeline: register-staged LDG of chunk kc+1 issued before computing chunk kc.
// One __syncthreads per chunk; two smem buffers.
#define KC 32
#define APITCH 36
#define ASTRIDE (128 * APITCH)

template <int BN, int SRC>
__global__ void __launch_bounds__(256, 2)
k_mma_dinv(const float* __restrict__ Aext, const float* __restrict__ Bg,
           int M, int K) {
    const float* __restrict__ A = (SRC == 0) ? Aext : g_x2;
    const int BPITCH  = BN + 8;
    const int BSTRIDE = KC * BPITCH;
    const int TPR     = BN / 4;        // B staging: threads per row
    const int KSTEP   = 256 / TPR;
    const int NB      = KC / KSTEP;    // B staging regs (float4 count)

    extern __shared__ float sm[];
    float* AsBase = sm;                        // 2 buffers
    float* BsBase = sm + 2 * ASTRIDE;

    int tid  = threadIdx.x;
    int warp = tid >> 5, lane = tid & 31;
    int wm = warp & 3, wn = warp >> 2;
    const int WNT = BN / 2;
    const int NF  = WNT / 8;
    int g  = lane >> 2, tg = lane & 3;
    int row0 = blockIdx.x * 128;

    // staging thread mapping
    int ar = tid >> 3, ac = (tid & 7) * 4;     // A: 4 rows of float4
    int bkr = tid / TPR, bbc = (tid % TPR) * 4;

    float4 av[4];
    float4 bv[NB];

    // ---- prologue: load chunk 0 ----
    #pragma unroll
    for (int i = 0; i < 4; i++) {
        int rr = ar + i * 32;
        av[i] = (row0 + rr < M)
            ? *reinterpret_cast<const float4*>(A + (size_t)(row0 + rr) * K + ac)
            : make_float4(0.f, 0.f, 0.f, 0.f);
    }
    #pragma unroll
    for (int i = 0; i < NB; i++) {
        int kk = bkr + i * KSTEP;
        bv[i] = *reinterpret_cast<const float4*>(Bg + (size_t)kk * BN + bbc);
    }

    float acc[2][NF][4];
    #pragma unroll
    for (int i = 0; i < 2; i++)
        #pragma unroll
        for (int j = 0; j < NF; j++)
            #pragma unroll
            for (int q = 0; q < 4; q++) acc[i][j][q] = 0.0f;

    const int NCHUNK = K / KC;
    for (int kc = 0; kc < NCHUNK; kc++) {
        float* As = AsBase + (kc & 1) * ASTRIDE;
        float* Bs = BsBase + (kc & 1) * BSTRIDE;

        // ---- store staged regs (tf32-rounded) ----
        #pragma unroll
        for (int i = 0; i < 4; i++)
            *reinterpret_cast<float4*>(&As[(ar + i * 32) * APITCH + ac]) = cvt4(av[i]);
        #pragma unroll
        for (int i = 0; i < NB; i++)
            *reinterpret_cast<float4*>(&Bs[(bkr + i * KSTEP) * BPITCH + bbc]) = cvt4(bv[i]);
        __syncthreads();

        // ---- issue next chunk's loads (overlap with compute below) ----
        if (kc + 1 < NCHUNK) {
            int k0 = (kc + 1) * KC;
            #pragma unroll
            for (int i = 0; i < 4; i++) {
                int rr = ar + i * 32;
                av[i] = (row0 + rr < M)
                    ? *reinterpret_cast<const float4*>(A + (size_t)(row0 + rr) * K + k0 + ac)
                    : make_float4(0.f, 0.f, 0.f, 0.f);
            }
            #pragma unroll
            for (int i = 0; i < NB; i++) {
                int kk = k0 + bkr + i * KSTEP;
                bv[i] = *reinterpret_cast<const float4*>(Bg + (size_t)kk * BN + bbc);
            }
        }

        // ---- compute chunk kc ----
        #pragma unroll
        for (int ks = 0; ks < KC; ks += 8) {
            float a[2][4];
            #pragma unroll
            for (int mf = 0; mf < 2; mf++) {
                int arr = wm * 32 + mf * 16;
                a[mf][0] = As[(arr + g)     * APITCH + ks + tg];
                a[mf][1] = As[(arr + g + 8) * APITCH + ks + tg];
                a[mf][2] = As[(arr + g)     * APITCH + ks + tg + 4];
                a[mf][3] = As[(arr + g + 8) * APITCH + ks + tg + 4];
            }
            #pragma unroll
            for (int nf = 0; nf < NF; nf++) {
                int bn0 = wn * WNT + nf * 8;
                float b0 = Bs[(ks + tg)     * BPITCH + bn0 + g];
                float b1 = Bs[(ks + tg + 4) * BPITCH + bn0 + g];
                #pragma unroll
                for (int mf = 0; mf < 2; mf++)
                    mma_tf32(acc[mf][nf], a[mf], b0, b1);
            }
        }
        // no trailing sync: next iteration stores to the OTHER buffer; the sync at the
        // top of that iteration (after its stores) also proves all threads finished
        // this buffer's compute before it is overwritten two chunks later.
    }

    #pragma unroll
    for (int mf = 0; mf < 2; mf++) {
        int r0 = row0 + wm * 32 + mf * 16 + g;
        int r1 = r0 + 8;
        float d0 = (r0 < M) ? g_dinv[r0] : 0.f;
        float d1 = (r1 < M) ? g_dinv[r1] : 0.f;
        #pragma unroll
        for (int nf = 0; nf < NF; nf++) {
            int cc = wn * WNT + nf * 8 + tg * 2;
            if (r0 < M) {
                g_hn[(size_t)r0 * BN + cc]     = acc[mf][nf][0] * d0;
                g_hn[(size_t)r0 * BN + cc + 1] = acc[mf][nf][1] * d0;
            }
            if (r1 < M) {
                g_hn[(size_t)r1 * BN + cc]     = acc[mf][nf][2] * d1;
                g_hn[(size_t)r1 * BN + cc + 1] = acc[mf][nf][3] * d1;
            }
        }
    }
}

#define SMEM_GEMM(BN) ((2 * ASTRIDE + 2 * KC * ((BN) + 8)) * 4)

// ---------------- aggregation: one warp per node, MLP-4 gathers ----------------
// x2[d] = relu( dinv[d]*(hn[d] + sum_{s in N(d)} hn[s]) + b1 )   (F=128, hn pre-scaled)
__global__ void k_agg128(const float* __restrict__ bias, int n_nodes) {
    int warp = (blockIdx.x * blockDim.x + threadIdx.x) >> 5;
    int lane = threadIdx.x & 31;
    if (warp >= n_nodes) return;
    int d = warp;
    const float* hn = g_hn;
    float4 acc = *reinterpret_cast<const float4*>(hn + (size_t)d * 128 + lane * 4);
    float4 acc2 = make_float4(0.f, 0.f, 0.f, 0.f);
    int e = g_start[d], e1 = g_end[d];
    for (; e + 4 <= e1; e += 4) {
        int s0 = g_srcsorted[e],     s1 = g_srcsorted[e + 1];
        int s2 = g_srcsorted[e + 2], s3 = g_srcsorted[e + 3];
        float4 v0 = *reinterpret_cast<const float4*>(hn + (size_t)s0 * 128 + lane * 4);
        float4 v1 = *reinterpret_cast<const float4*>(hn + (size_t)s1 * 128 + lane * 4);
        float4 v2 = *reinterpret_cast<const float4*>(hn + (size_t)s2 * 128 + lane * 4);
        float4 v3 = *reinterpret_cast<const float4*>(hn + (size_t)s3 * 128 + lane * 4);
        acc.x += v0.x; acc.y += v0.y; acc.z += v0.z; acc.w += v0.w;
        acc2.x += v1.x; acc2.y += v1.y; acc2.z += v1.z; acc2.w += v1.w;
        acc.x += v2.x; acc.y += v2.y; acc.z += v2.z; acc.w += v2.w;
        acc2.x += v3.x; acc2.y += v3.y; acc2.z += v3.z; acc2.w += v3.w;
    }
    for (; e < e1; e++) {
        int s = g_srcsorted[e];
        float4 v = *reinterpret_cast<const float4*>(hn + (size_t)s * 128 + lane * 4);
        acc.x += v.x; acc.y += v.y; acc.z += v.z; acc.w += v.w;
    }
    acc.x += acc2.x; acc.y += acc2.y; acc.z += acc2.z; acc.w += acc2.w;
    float dv = g_dinv[d];
    float4 bv = *reinterpret_cast<const float4*>(bias + lane * 4);
    float4 o;
    o.x = fmaxf(fmaf(acc.x, dv, bv.x), 0.f);
    o.y = fmaxf(fmaf(acc.y, dv, bv.y), 0.f);
    o.z = fmaxf(fmaf(acc.z, dv, bv.z), 0.f);
    o.w = fmaxf(fmaf(acc.w, dv, bv.w), 0.f);
    *reinterpret_cast<float4*>(g_x2 + (size_t)d * 128 + lane * 4) = o;
}

// out[d] = dinv[d]*(hn[d] + sum hn[s]) + b2   (F=64, no relu, hn pre-scaled)
__global__ void k_agg64(const float* __restrict__ bias,
                        float* __restrict__ out, int n_nodes) {
    int warp = (blockIdx.x * blockDim.x + threadIdx.x) >> 5;
    int lane = threadIdx.x & 31;
    if (warp >= n_nodes) return;
    int d = warp;
    const float* hn = g_hn;
    float2 acc = *reinterpret_cast<const float2*>(hn + (size_t)d * 64 + lane * 2);
    float2 acc2 = make_float2(0.f, 0.f);
    int e = g_start[d], e1 = g_end[d];
    for (; e + 4 <= e1; e += 4) {
        int s0 = g_srcsorted[e],     s1 = g_srcsorted[e + 1];
        int s2 = g_srcsorted[e + 2], s3 = g_srcsorted[e + 3];
        float2 v0 = *reinterpret_cast<const float2*>(hn + (size_t)s0 * 64 + lane * 2);
        float2 v1 = *reinterpret_cast<const float2*>(hn + (size_t)s1 * 64 + lane * 2);
        float2 v2 = *reinterpret_cast<const float2*>(hn + (size_t)s2 * 64 + lane * 2);
        float2 v3 = *reinterpret_cast<const float2*>(hn + (size_t)s3 * 64 + lane * 2);
        acc.x += v0.x; acc.y += v0.y;
        acc2.x += v1.x; acc2.y += v1.y;
        acc.x += v2.x; acc.y += v2.y;
        acc2.x += v3.x; acc2.y += v3.y;
    }
    for (; e < e1; e++) {
        int s = g_srcsorted[e];
        float2 v = *reinterpret_cast<const float2*>(hn + (size_t)s * 64 + lane * 2);
        acc.x += v.x; acc.y += v.y;
    }
    acc.x += acc2.x; acc.y += acc2.y;
    float dv = g_dinv[d];
    float2 bv = *reinterpret_cast<const float2*>(bias + lane * 2);
    float2 o;
    o.x = fmaf(acc.x, dv, bv.x);
    o.y = fmaf(acc.y, dv, bv.y);
    *reinterpret_cast<float2*>(out + (size_t)d * 64 + lane * 2) = o;
}

// ---------------- launch ----------------
extern "C" void kernel_launch(void* const* d_in, const int* in_sizes, int n_in,
                              void* d_out, int out_size) {
    const float* x  = (const float*)d_in[0];
    const int*   ei = (const int*)d_in[1];     // int32 [2, E]
    const float* W1 = (const float*)d_in[2];
    const float* b1 = (const float*)d_in[3];
    const float* W2 = (const float*)d_in[4];
    const float* b2 = (const float*)d_in[5];
    float* out = (float*)d_out;

    int n_nodes = in_sizes[0] / FIN;       // 100000
    int n_edges = in_sizes[1] / 2;         // 600000

    int nb_edges = (n_edges + 255) / 256;
    int nb_scan  = (n_nodes + 1023) / 1024;
    int nb_gemm  = (n_nodes + 127) / 128;
    int nb_agg   = (n_nodes * 32 + 255) / 256;

    // one-time stream/event/attr setup (first call is the uncaptured correctness run)
    static cudaStream_t s2 = nullptr;
    static cudaEvent_t evFork = nullptr, evJoin = nullptr;
    if (!s2) {
        cudaStreamCreateWithFlags(&s2, cudaStreamNonBlocking);
        cudaEventCreateWithFlags(&evFork, cudaEventDisableTiming);
        cudaEventCreateWithFlags(&evJoin, cudaEventDisableTiming);
        cudaFuncSetAttribute(k_mma_dinv<FHID, 0>,
                             cudaFuncAttributeMaxDynamicSharedMemorySize, SMEM_GEMM(FHID));
        cudaFuncSetAttribute(k_mma_dinv<FOUT, 1>,
                             cudaFuncAttributeMaxDynamicSharedMemorySize, SMEM_GEMM(FOUT));
    }

    // ---- CSR: hist -> scan (main stream; GEMM1 needs dinv from scan) ----
    k_hist<<<nb_edges, 256>>>(ei, n_edges, n_nodes);
    k_scan<<<nb_scan, 256>>>(n_nodes);

    // ---- narrow fork: fill (s2) overlaps GEMM1 (main) ----
    cudaEventRecord(evFork, 0);
    cudaStreamWaitEvent(s2, evFork, 0);
    k_fill<<<nb_edges, 256, 0, s2>>>(ei, n_edges, n_nodes);
    cudaEventRecord(evJoin, s2);

    k_mma_dinv<FHID, 0><<<nb_gemm, 256, SMEM_GEMM(FHID)>>>(x, W1, n_nodes, FIN);

    cudaStreamWaitEvent(0, evJoin, 0);   // join: adjacency ready

    // ---- layer 1 aggregation ----
    k_agg128<<<nb_agg, 256>>>(b1, n_nodes);

    // ---- layer 2 ----
    k_mma_dinv<FOUT, 1><<<nb_gemm, 256, SMEM_GEMM(FOUT)>>>(nullptr, W2, n_nodes, FHID);
    k_agg64<<<nb_agg, 256>>>(b2, out, n_nodes);
}

// round 11
// speedup vs baseline: 1.1906x; 1.0138x over previous
#include <cuda_runtime.h>
#include <cstdint>

// ---------------- problem constants ----------------
#define NMAX 100000
#define EMAX 600000
#define FIN  128
#define FHID 128
#define FOUT 64

// ---------------- scratch (static device globals; zero-initialized at load) ----------------
__device__ __align__(16) float g_hn[(size_t)NMAX * FHID];   // per-layer GEMM out (pre-agg)
__device__ __align__(16) float g_x2[(size_t)NMAX * FHID];   // layer-2 input
__device__ __align__(16) float g_dinv[NMAX];
__device__ int   g_count[NMAX];     // zeroed by k_scan after reading (self-cleaning)
__device__ int   g_start[NMAX];
__device__ int   g_end[NMAX];
__device__ int   g_cursor[NMAX];
__device__ int   g_srcsorted[EMAX];
__device__ int   g_total;           // zeroed by k_fill after scan consumed it

// ---------------- degree / CSR build ----------------
// edge_index is int32, layout [2, E]: src = ei[e], dst = ei[E + e]
__global__ void k_hist(const int* __restrict__ ei, int n_edges, int n_nodes) {
    int e = blockIdx.x * blockDim.x + threadIdx.x;
    if (e < n_edges) {
        int d = ei[n_edges + e];
        if ((unsigned)d < (unsigned)n_nodes) atomicAdd(&g_count[d], 1);
    }
}

// ONE-PASS order-free scan: per-block local prefix + atomic base grab.
// Consumes g_count (re-zeros it for the next replay), writes start/end/cursor/dinv.
__global__ void k_scan(int n) {
    __shared__ int s[256];
    __shared__ int base_sh;
    int t = threadIdx.x;
    int blk = blockIdx.x * 1024;
    int vals[4];
    int tsum = 0;
    #pragma unroll
    for (int k = 0; k < 4; k++) {
        int i = blk + t * 4 + k;
        vals[k] = (i < n) ? g_count[i] : 0;
        tsum += vals[k];
    }
    s[t] = tsum;
    __syncthreads();
    for (int off = 1; off < 256; off <<= 1) {
        int x = (t >= off) ? s[t - off] : 0;
        __syncthreads();
        s[t] += x;
        __syncthreads();
    }
    if (t == 255) base_sh = atomicAdd(&g_total, s[255]);
    __syncthreads();
    int texcl = s[t] - tsum + base_sh;
    int run = 0;
    #pragma unroll
    for (int k = 0; k < 4; k++) {
        int i = blk + t * 4 + k;
        if (i < n) {
            int o = texcl + run;
            g_start[i]  = o;
            g_end[i]    = o + vals[k];
            g_cursor[i] = o;
            g_dinv[i]   = rsqrtf((float)(vals[k] + 1));   // +1 self loop
            g_count[i]  = 0;                              // self-clean for next replay
        }
        run += vals[k];
    }
}

__global__ void k_fill(const int* __restrict__ ei, int n_edges, int n_nodes) {
    int e = blockIdx.x * blockDim.x + threadIdx.x;
    if (e == 0) g_total = 0;        // self-clean (scan already consumed it)
    if (e < n_edges) {
        int srcv = ei[e];
        int d    = ei[n_edges + e];
        if ((unsigned)d < (unsigned)n_nodes && (unsigned)srcv < (unsigned)n_nodes) {
            int p = atomicAdd(&g_cursor[d], 1);
            g_srcsorted[p] = srcv;
        }
    }
}

// ---------------- TF32 / cp.async helpers ----------------
__device__ __forceinline__ float to_tf32(float x) {
    uint32_t u;
    asm("cvt.rna.tf32.f32 %0, %1;" : "=r"(u) : "f"(x));
    return __uint_as_float(u);
}

__device__ __forceinline__ void mma_tf32(float c[4], const float a[4], float b0, float b1) {
    uint32_t const* A = reinterpret_cast<uint32_t const*>(a);
    uint32_t B0 = __float_as_uint(b0), B1 = __float_as_uint(b1);
    asm volatile(
        "mma.sync.aligned.m16n8k8.row.col.f32.tf32.tf32.f32 "
        "{%0,%1,%2,%3}, {%4,%5,%6,%7}, {%8,%9}, {%0,%1,%2,%3};"
        : "+f"(c[0]), "+f"(c[1]), "+f"(c[2]), "+f"(c[3])
        : "r"(A[0]), "r"(A[1]), "r"(A[2]), "r"(A[3]), "r"(B0), "r"(B1));
}

__device__ __forceinline__ void cp_async16(float* smem_ptr, const float* gptr, bool valid) {
    uint32_t sa = (uint32_t)__cvta_generic_to_shared(smem_ptr);
    int sz = valid ? 16 : 0;
    asm volatile("cp.async.cg.shared.global [%0], [%1], 16, %2;"
                 :: "r"(sa), "l"(gptr), "r"(sz));
}
#define CP_COMMIT() asm volatile("cp.async.commit_group;" ::: "memory")
#define CP_WAIT(N)  asm volatile("cp.async.wait_group %0;" :: "n"(N) : "memory")

// ---------------- cp.async double-buffered TF32 GEMM with fused dinv epilogue ----------------
// g_hn[m,n] = g_dinv[m] * sum_k A[m,k]*B[k,n]
// TM=64 rows per CTA, 8 warps = 2(M) x 4(N), 3 CTAs/SM for latency hiding.
#define KC 32
#define TM 64
#define AP 36
#define ASTRIDE (TM * AP)       // 2304 floats per A buffer

template <int BN, int SRC>
__global__ void __launch_bounds__(256, 3)
k_mma_dinv(const float* __restrict__ Aext, const float* __restrict__ Bg,
           int M, int K) {
    const float* __restrict__ A = (SRC == 0) ? Aext : g_x2;
    const int BPITCH  = BN + 8;
    const int BSTRIDE = KC * BPITCH;
    const int BTPR    = BN / 4;        // B staging: threads per row
    const int BKSTEP  = 256 / BTPR;
    const int NBB     = KC / BKSTEP;   // B float4s per thread per chunk

    extern __shared__ float sm[];
    float* As0 = sm;                    // 2 x ASTRIDE
    float* Bs0 = sm + 2 * ASTRIDE;      // 2 x BSTRIDE

    int tid  = threadIdx.x;
    int warp = tid >> 5, lane = tid & 31;
    int wm = warp & 1, wn = warp >> 1;  // 2(M) x 4(N)
    const int WNT = BN / 4;
    const int NF  = WNT / 8;
    int g  = lane >> 2, tg = lane & 3;
    int row0 = blockIdx.x * TM;

    // staging thread mapping
    int ar = tid >> 3, ac = (tid & 7) * 4;      // A: rows ar, ar+32
    int bkr = tid / BTPR, bbc = (tid % BTPR) * 4;

    auto issue = [&](int kc) {
        float* As = As0 + (kc & 1) * ASTRIDE;
        float* Bs = Bs0 + (kc & 1) * BSTRIDE;
        int k0 = kc * KC;
        #pragma unroll
        for (int i = 0; i < 2; i++) {
            int rr = ar + i * 32;
            cp_async16(&As[rr * AP + ac],
                       A + (size_t)(row0 + rr) * K + k0 + ac,
                       row0 + rr < M);
        }
        #pragma unroll
        for (int i = 0; i < NBB; i++) {
            int kk = bkr + i * BKSTEP;
            cp_async16(&Bs[kk * BPITCH + bbc],
                       Bg + (size_t)(k0 + kk) * BN + bbc, true);
        }
    };

    float acc[2][NF][4];
    #pragma unroll
    for (int i = 0; i < 2; i++)
        #pragma unroll
        for (int j = 0; j < NF; j++)
            #pragma unroll
            for (int q = 0; q < 4; q++) acc[i][j][q] = 0.0f;

    issue(0); CP_COMMIT();

    const int NCHUNK = K / KC;
    for (int kc = 0; kc < NCHUNK; kc++) {
        if (kc + 1 < NCHUNK) { issue(kc + 1); CP_COMMIT(); CP_WAIT(1); }
        else                 { CP_WAIT(0); }
        __syncthreads();                       // chunk kc visible to all

        float* As = As0 + (kc & 1) * ASTRIDE;
        float* Bs = Bs0 + (kc & 1) * BSTRIDE;

        #pragma unroll
        for (int ks = 0; ks < KC; ks += 8) {
            float a[2][4];
            #pragma unroll
            for (int mf = 0; mf < 2; mf++) {
                int arr = wm * 32 + mf * 16;
                a[mf][0] = to_tf32(As[(arr + g)     * AP + ks + tg]);
                a[mf][1] = to_tf32(As[(arr + g + 8) * AP + ks + tg]);
                a[mf][2] = to_tf32(As[(arr + g)     * AP + ks + tg + 4]);
                a[mf][3] = to_tf32(As[(arr + g + 8) * AP + ks + tg + 4]);
            }
            #pragma unroll
            for (int nf = 0; nf < NF; nf++) {
                int bn0 = wn * WNT + nf * 8;
                float b0 = to_tf32(Bs[(ks + tg)     * BPITCH + bn0 + g]);
                float b1 = to_tf32(Bs[(ks + tg + 4) * BPITCH + bn0 + g]);
                #pragma unroll
                for (int mf = 0; mf < 2; mf++)
                    mma_tf32(acc[mf][nf], a[mf], b0, b1);
            }
        }
        __syncthreads();   // compute(kc) done before iter kc+2 overwrites this buffer
    }

    #pragma unroll
    for (int mf = 0; mf < 2; mf++) {
        int r0 = row0 + wm * 32 + mf * 16 + g;
        int r1 = r0 + 8;
        float d0 = (r0 < M) ? g_dinv[r0] : 0.f;
        float d1 = (r1 < M) ? g_dinv[r1] : 0.f;
        #pragma unroll
        for (int nf = 0; nf < NF; nf++) {
            int cc = wn * WNT + nf * 8 + tg * 2;
            if (r0 < M) {
                g_hn[(size_t)r0 * BN + cc]     = acc[mf][nf][0] * d0;
                g_hn[(size_t)r0 * BN + cc + 1] = acc[mf][nf][1] * d0;
            }
            if (r1 < M) {
                g_hn[(size_t)r1 * BN + cc]     = acc[mf][nf][2] * d1;
                g_hn[(size_t)r1 * BN + cc + 1] = acc[mf][nf][3] * d1;
            }
        }
    }
}

#define SMEM_GEMM(BN) ((2 * ASTRIDE + 2 * KC * ((BN) + 8)) * 4)

// ---------------- aggregation: one warp per node, MLP-4 gathers ----------------
// x2[d] = relu( dinv[d]*(hn[d] + sum_{s in N(d)} hn[s]) + b1 )   (F=128, hn pre-scaled)
__global__ void k_agg128(const float* __restrict__ bias, int n_nodes) {
    int warp = (blockIdx.x * blockDim.x + threadIdx.x) >> 5;
    int lane = threadIdx.x & 31;
    if (warp >= n_nodes) return;
    int d = warp;
    const float* hn = g_hn;
    float4 acc = *reinterpret_cast<const float4*>(hn + (size_t)d * 128 + lane * 4);
    float4 acc2 = make_float4(0.f, 0.f, 0.f, 0.f);
    int e = g_start[d], e1 = g_end[d];
    for (; e + 4 <= e1; e += 4) {
        int s0 = g_srcsorted[e],     s1 = g_srcsorted[e + 1];
        int s2 = g_srcsorted[e + 2], s3 = g_srcsorted[e + 3];
        float4 v0 = *reinterpret_cast<const float4*>(hn + (size_t)s0 * 128 + lane * 4);
        float4 v1 = *reinterpret_cast<const float4*>(hn + (size_t)s1 * 128 + lane * 4);
        float4 v2 = *reinterpret_cast<const float4*>(hn + (size_t)s2 * 128 + lane * 4);
        float4 v3 = *reinterpret_cast<const float4*>(hn + (size_t)s3 * 128 + lane * 4);
        acc.x += v0.x; acc.y += v0.y; acc.z += v0.z; acc.w += v0.w;
        acc2.x += v1.x; acc2.y += v1.y; acc2.z += v1.z; acc2.w += v1.w;
        acc.x += v2.x; acc.y += v2.y; acc.z += v2.z; acc.w += v2.w;
        acc2.x += v3.x; acc2.y += v3.y; acc2.z += v3.z; acc2.w += v3.w;
    }
    for (; e < e1; e++) {
        int s = g_srcsorted[e];
        float4 v = *reinterpret_cast<const float4*>(hn + (size_t)s * 128 + lane * 4);
        acc.x += v.x; acc.y += v.y; acc.z += v.z; acc.w += v.w;
    }
    acc.x += acc2.x; acc.y += acc2.y; acc.z += acc2.z; acc.w += acc2.w;
    float dv = g_dinv[d];
    float4 bv = *reinterpret_cast<const float4*>(bias + lane * 4);
    float4 o;
    o.x = fmaxf(fmaf(acc.x, dv, bv.x), 0.f);
    o.y = fmaxf(fmaf(acc.y, dv, bv.y), 0.f);
    o.z = fmaxf(fmaf(acc.z, dv, bv.z), 0.f);
    o.w = fmaxf(fmaf(acc.w, dv, bv.w), 0.f);
    *reinterpret_cast<float4*>(g_x2 + (size_t)d * 128 + lane * 4) = o;
}

// out[d] = dinv[d]*(hn[d] + sum hn[s]) + b2   (F=64, no relu, hn pre-scaled)
__global__ void k_agg64(const float* __restrict__ bias,
                        float* __restrict__ out, int n_nodes) {
    int warp = (blockIdx.x * blockDim.x + threadIdx.x) >> 5;
    int lane = threadIdx.x & 31;
    if (warp >= n_nodes) return;
    int d = warp;
    const float* hn = g_hn;
    float2 acc = *reinterpret_cast<const float2*>(hn + (size_t)d * 64 + lane * 2);
    float2 acc2 = make_float2(0.f, 0.f);
    int e = g_start[d], e1 = g_end[d];
    for (; e + 4 <= e1; e += 4) {
        int s0 = g_srcsorted[e],     s1 = g_srcsorted[e + 1];
        int s2 = g_srcsorted[e + 2], s3 = g_srcsorted[e + 3];
        float2 v0 = *reinterpret_cast<const float2*>(hn + (size_t)s0 * 64 + lane * 2);
        float2 v1 = *reinterpret_cast<const float2*>(hn + (size_t)s1 * 64 + lane * 2);
        float2 v2 = *reinterpret_cast<const float2*>(hn + (size_t)s2 * 64 + lane * 2);
        float2 v3 = *reinterpret_cast<const float2*>(hn + (size_t)s3 * 64 + lane * 2);
        acc.x += v0.x; acc.y += v0.y;
        acc2.x += v1.x; acc2.y += v1.y;
        acc.x += v2.x; acc.y += v2.y;
        acc2.x += v3.x; acc2.y += v3.y;
    }
    for (; e < e1; e++) {
        int s = g_srcsorted[e];
        float2 v = *reinterpret_cast<const float2*>(hn + (size_t)s * 64 + lane * 2);
        acc.x += v.x; acc.y += v.y;
    }
    acc.x += acc2.x; acc.y += acc2.y;
    float dv = g_dinv[d];
    float2 bv = *reinterpret_cast<const float2*>(bias + lane * 2);
    float2 o;
    o.x = fmaf(acc.x, dv, bv.x);
    o.y = fmaf(acc.y, dv, bv.y);
    *reinterpret_cast<float2*>(out + (size_t)d * 64 + lane * 2) = o;
}

// ---------------- launch ----------------
extern "C" void kernel_launch(void* const* d_in, const int* in_sizes, int n_in,
                              void* d_out, int out_size) {
    const float* x  = (const float*)d_in[0];
    const int*   ei = (const int*)d_in[1];     // int32 [2, E]
    const float* W1 = (const float*)d_in[2];
    const float* b1 = (const float*)d_in[3];
    const float* W2 = (const float*)d_in[4];
    const float* b2 = (const float*)d_in[5];
    float* out = (float*)d_out;

    int n_nodes = in_sizes[0] / FIN;       // 100000
    int n_edges = in_sizes[1] / 2;         // 600000

    int nb_edges = (n_edges + 255) / 256;
    int nb_scan  = (n_nodes + 1023) / 1024;
    int nb_gemm  = (n_nodes + TM - 1) / TM;
    int nb_agg   = (n_nodes * 32 + 255) / 256;

    // one-time stream/event/attr setup (first call is the uncaptured correctness run)
    static cudaStream_t s2 = nullptr;
    static cudaEvent_t evFork = nullptr, evJoin = nullptr;
    if (!s2) {
        cudaStreamCreateWithFlags(&s2, cudaStreamNonBlocking);
        cudaEventCreateWithFlags(&evFork, cudaEventDisableTiming);
        cudaEventCreateWithFlags(&evJoin, cudaEventDisableTiming);
        cudaFuncSetAttribute(k_mma_dinv<FHID, 0>,
                             cudaFuncAttributeMaxDynamicSharedMemorySize, SMEM_GEMM(FHID));
        cudaFuncSetAttribute(k_mma_dinv<FOUT, 1>,
                             cudaFuncAttributeMaxDynamicSharedMemorySize, SMEM_GEMM(FOUT));
    }

    // ---- CSR: hist -> scan (main stream; GEMM1 needs dinv from scan) ----
    k_hist<<<nb_edges, 256>>>(ei, n_edges, n_nodes);
    k_scan<<<nb_scan, 256>>>(n_nodes);

    // ---- narrow fork: fill (s2) overlaps GEMM1 (main) ----
    cudaEventRecord(evFork, 0);
    cudaStreamWaitEvent(s2, evFork, 0);
    k_fill<<<nb_edges, 256, 0, s2>>>(ei, n_edges, n_nodes);
    cudaEventRecord(evJoin, s2);

    k_mma_dinv<FHID, 0><<<nb_gemm, 256, SMEM_GEMM(FHID)>>>(x, W1, n_nodes, FIN);

    cudaStreamWaitEvent(0, evJoin, 0);   // join: adjacency ready

    // ---- layer 1 aggregation ----
    k_agg128<<<nb_agg, 256>>>(b1, n_nodes);

    // ---- layer 2 ----
    k_mma_dinv<FOUT, 1><<<nb_gemm, 256, SMEM_GEMM(FOUT)>>>(nullptr, W2, n_nodes, FHID);
    k_agg64<<<nb_agg, 256>>>(b2, out, n_nodes);
}